// round 13
// baseline (speedup 1.0000x reference)
#include <cuda_runtime.h>
#include <cuda_fp16.h>
#include <cstdint>

// ---------------------------------------------------------------------------
// GNN_6837587935613: RGCN(mean, R=8) -> TransformerConv(1 head) -> BN+LeakyReLU
// N=50000, E=800000, G_DIM=512, H1=H2=128, R=8
// Round 13: PDL (programmatic dependent launch) on the critical chain to hide
//           launch/tail gaps; cp.async.ca for reused B tiles. Numerics = R11.
// ---------------------------------------------------------------------------

#define NN   50000
#define NPAD 50176
#define EE   800000
#define GD   512
#define HD   128
#define RR   8
#define NBS  196   // ceil(NN/256) scan blocks

// ---- scratch (device globals) ----
__device__ __align__(128) __half g_xWh[(size_t)NN * 1024];  // [N, 8*128] fp16
__device__ float4   g_h [(size_t)NN * 32];    // [N, 128] f32 (root+bias)
__device__ float4   g_q [(size_t)NN * 32];    // [N, 128] f32
__device__ __align__(128) __half g_kvh[(size_t)NN * 256];   // [N][32 grp][k4,v4]
__device__ int      g_cnt[NN * RR];
__device__ int      g_deg[NN];
__device__ int      g_off[NN];
__device__ int      g_fill[NN];
__device__ int      g_bsum[256];
__device__ unsigned g_csr[EE];
__device__ float    g_bnsum[HD];
__device__ float    g_bnsq[HD];
__device__ int      g_idx64;

// fp16 operands (row-padded; padding stays zero from load-time .bss init)
__device__ __align__(128) __half g_Ah[(size_t)NPAD * GD];
__device__ __align__(128) __half g_Hh[(size_t)NPAD * HD];   // hi(h)
__device__ __align__(128) __half g_Hl[(size_t)NPAD * HD];   // lo(h)
// K-major fp16 weights
__device__ __align__(128) __half g_Wall[9 * HD * GD];       // 8 relations + root
__device__ __align__(128) __half g_Wqk_hi[4 * HD * HD];

// ---------------------------------------------------------------------------
__device__ __forceinline__ uint32_t smem_u32(const void* p) {
    uint32_t a;
    asm("{ .reg .u64 t; cvta.to.shared.u64 t, %1; cvt.u32.u64 %0, t; }"
        : "=r"(a) : "l"(p));
    return a;
}
#define SWZ(o) ((o) ^ (((o) >> 3) & 0x70))

#define CP_ASYNC16(dst, src) \
    asm volatile("cp.async.cg.shared.global [%0], [%1], 16;" :: "r"(dst), "l"(src))
#define CP_ASYNC16_CA(dst, src) \
    asm volatile("cp.async.ca.shared.global [%0], [%1], 16;" :: "r"(dst), "l"(src))
#define CP_COMMIT()  asm volatile("cp.async.commit_group;" ::: "memory")
#define CP_WAIT0()   asm volatile("cp.async.wait_group 0;" ::: "memory")
#define CP_WAIT1()   asm volatile("cp.async.wait_group 1;" ::: "memory")

#define LDSM_X4(r, a)                                                        \
    asm volatile("ldmatrix.sync.aligned.m8n8.x4.shared.b16 {%0,%1,%2,%3}, [%4];" \
        : "=r"((r)[0]), "=r"((r)[1]), "=r"((r)[2]), "=r"((r)[3]) : "r"(a))

#define MMA16816(c, a, b0, b1)                                               \
    asm volatile("mma.sync.aligned.m16n8k16.row.col.f32.f16.f16.f32 "        \
        "{%0,%1,%2,%3}, {%4,%5,%6,%7}, {%8,%9}, {%0,%1,%2,%3};"              \
        : "+f"((c)[0]), "+f"((c)[1]), "+f"((c)[2]), "+f"((c)[3])             \
        : "r"((a)[0]), "r"((a)[1]), "r"((a)[2]), "r"((a)[3]), "r"(b0), "r"(b1))

// mode: 0 = f32 plain; 1 = fp16 plain (ldc in halves); 2 = fp16 kv k-slot;
//       3 = fp16 kv v-slot (kv row = 32 groups of [k0..k3, v0..v3])
struct OutDesc { void* C; const float* bias; long ldc; int mode; };
struct OutPack { OutDesc d[9]; };

// ---------------------------------------------------------------------------
// fp16 GEMM via mma.sync, 3-stage cp.async pipeline. NPASS=1: C = A@B^T.
// NPASS=2: C = Ahi@B^T + Alo@B^T. PDL: sync before first load, trigger at
// epilogue. Staged smem epilogue with coalesced copy-out.
// ---------------------------------------------------------------------------
template <int NPASS>
__global__ void __launch_bounds__(256, 2) mmagemm_k(
    const __half* __restrict__ Ahi, const __half* __restrict__ Alo,
    const __half* __restrict__ Bhi,
    OutPack outs, int M, int K, long bzStride)
{
    extern __shared__ char smem[];
    const uint32_t sb = smem_u32(smem);
    const int tid = threadIdx.x, lane = tid & 31, wid = tid >> 5;
    const int wm = wid & 3, wn = wid >> 2;
    const int z = blockIdx.x, row0 = blockIdx.y * 128;
    const __half* Bh = Bhi + (long)z * bzStride;

    const int KC = K >> 6;
    const int NIT = NPASS * KC;

    float acc[2][8][4];
#pragma unroll
    for (int i = 0; i < 2; i++)
#pragma unroll
        for (int j = 0; j < 8; j++)
#pragma unroll
            for (int c = 0; c < 4; c++) acc[i][j][c] = 0.f;

    const int cr = tid >> 3, cck = tid & 7;

    auto issue = [&](int it) {
        const int pass = it / KC;
        const int k0 = (it - pass * KC) * 64;
        const __half* Ap = (NPASS == 2 && pass == 1) ? Alo : Ahi;
        const uint32_t base = sb + (it % 3) * 32768;
#pragma unroll
        for (int i = 0; i < 4; i++) {
            const int r = cr + i * 32;
            CP_ASYNC16(base + SWZ(r * 128 + cck * 16),
                       Ap + (size_t)(row0 + r) * K + k0 + cck * 8);
            CP_ASYNC16_CA(base + 16384 + SWZ(r * 128 + cck * 16),
                          Bh + (size_t)r * K + k0 + cck * 8);
        }
        CP_COMMIT();
    };

    cudaGridDependencySynchronize();   // PDL: producer data ready

    issue(0);
    if (NIT > 1) issue(1);
    for (int it = 0; it < NIT; ++it) {
        if (it + 1 < NIT) CP_WAIT1();
        else              CP_WAIT0();
        __syncthreads();
        if (it + 2 < NIT) issue(it + 2);

        const uint32_t Ab = sb + (it % 3) * 32768;
        const uint32_t Bb = Ab + 16384;
#pragma unroll
        for (int ks = 0; ks < 4; ks++) {
            uint32_t ra[2][4];
#pragma unroll
            for (int mi = 0; mi < 2; mi++) {
                const int r = wm * 32 + mi * 16 + (lane & 15);
                const int ck = ks * 2 + (lane >> 4);
                LDSM_X4(ra[mi], Ab + SWZ(r * 128 + ck * 16));
            }
            uint32_t rb[4][4];
#pragma unroll
            for (int g = 0; g < 4; g++) {
                const int nr = wn * 64 + g * 16 + ((lane & 7) | ((lane & 16) >> 1));
                const int ck = ks * 2 + ((lane >> 3) & 1);
                LDSM_X4(rb[g], Bb + SWZ(nr * 128 + ck * 16));
            }
#pragma unroll
            for (int mi = 0; mi < 2; mi++)
#pragma unroll
                for (int g = 0; g < 4; g++) {
                    MMA16816(acc[mi][2 * g + 0], ra[mi], rb[g][0], rb[g][1]);
                    MMA16816(acc[mi][2 * g + 1], ra[mi], rb[g][2], rb[g][3]);
                }
        }
    }

    cudaTriggerProgrammaticLaunchCompletion();   // let the dependent launch

    // ---- staged epilogue ----
    __syncthreads();
    const OutDesc od = outs.d[z];

    if (od.mode == 0) {
        float* st = (float*)smem;                 // [128][132] f32
#pragma unroll
        for (int mi = 0; mi < 2; mi++) {
            const int rl = wm * 32 + mi * 16 + (lane >> 2);
#pragma unroll
            for (int ni = 0; ni < 8; ni++) {
                const int cl = wn * 64 + ni * 8 + (lane & 3) * 2;
                float b0 = 0.f, b1 = 0.f;
                if (od.bias) { b0 = od.bias[cl]; b1 = od.bias[cl + 1]; }
#pragma unroll
                for (int hr = 0; hr < 2; hr++) {
                    float2 v = { acc[mi][ni][2 * hr + 0] + b0,
                                 acc[mi][ni][2 * hr + 1] + b1 };
                    *(float2*)(st + (rl + hr * 8) * 132 + cl) = v;
                }
            }
        }
        __syncthreads();
#pragma unroll
        for (int i = 0; i < 16; i++) {
            int chunk = tid + i * 256;
            int rl = chunk >> 5, c4 = chunk & 31;
            int row = row0 + rl;
            if (row < M) {
                uint4 v = *(uint4*)(st + rl * 132 + c4 * 4);
                *(uint4*)((float*)od.C + (size_t)row * od.ldc + c4 * 4) = v;
            }
        }
    } else {
        __half* st = (__half*)smem;               // [128][136] fp16
#pragma unroll
        for (int mi = 0; mi < 2; mi++) {
            const int rl = wm * 32 + mi * 16 + (lane >> 2);
#pragma unroll
            for (int ni = 0; ni < 8; ni++) {
                const int cl = wn * 64 + ni * 8 + (lane & 3) * 2;
                float b0 = 0.f, b1 = 0.f;
                if (od.bias) { b0 = od.bias[cl]; b1 = od.bias[cl + 1]; }
#pragma unroll
                for (int hr = 0; hr < 2; hr++) {
                    __half2 hv = __floats2half2_rn(acc[mi][ni][2 * hr + 0] + b0,
                                                   acc[mi][ni][2 * hr + 1] + b1);
                    *(__half2*)(st + (rl + hr * 8) * 136 + cl) = hv;
                }
            }
        }
        __syncthreads();
        if (od.mode == 1) {
#pragma unroll
            for (int i = 0; i < 8; i++) {
                int chunk = tid + i * 256;
                int rl = chunk >> 4, c4 = chunk & 15;
                int row = row0 + rl;
                if (row < M) {
                    uint4 v = *(uint4*)(st + rl * 136 + c4 * 8);
                    *(uint4*)((__half*)od.C + (size_t)row * od.ldc + c4 * 8) = v;
                }
            }
        } else {
            const int voff = (od.mode == 3) ? 4 : 0;
#pragma unroll
            for (int i = 0; i < 16; i++) {
                int chunk = tid + i * 256;
                int rl = chunk >> 5, g = chunk & 31;
                int row = row0 + rl;
                if (row < M) {
                    uint2 v = *(uint2*)(st + rl * 136 + g * 4);
                    *(uint2*)((__half*)od.C + (size_t)row * 256 + g * 8 + voff) = v;
                }
            }
        }
    }
}

// ---------------------------------------------------------------------------
// merged weight prep + x->fp16 conversion (one launch)
// ---------------------------------------------------------------------------
__global__ void prepcvt_k(const float* __restrict__ Wrel, const float* __restrict__ Wroot,
                          const float* __restrict__ Wq, const float* __restrict__ Wk,
                          const float* __restrict__ Wv, const float* __restrict__ Ws,
                          const float* __restrict__ x) {
    const int T0 = 9 * GD * HD;
    const int T1 = T0 + 4 * HD * HD;
    const int T2 = T1 + NN * GD / 4;
    int i = blockIdx.x * blockDim.x + threadIdx.x;
    if (i >= T2) return;
    if (i < T0) {
        int z = i >> 16, rem = i & 65535;
        int k = rem >> 7, n = rem & 127;
        float v = (z < 8) ? Wrel[(long)z * 65536 + k * 128 + n] : Wroot[k * 128 + n];
        g_Wall[(long)z * 65536 + n * 512 + k] = __float2half(v);
    } else if (i < T1) {
        int j = i - T0;
        int m = j >> 14, jj = j & 16383;
        int k = jj >> 7, n = jj & 127;
        float v = (m == 0) ? Wq[jj] : (m == 1) ? Wk[jj] : (m == 2) ? Wv[jj] : Ws[jj];
        g_Wqk_hi[(long)m * 16384 + n * 128 + k] = __float2half_rn(v);
    } else {
        long e = (long)(i - T1) * 4;
        float4 v = *(const float4*)(x + e);
        *(__half2*)(g_Ah + e)     = __floats2half2_rn(v.x, v.y);
        *(__half2*)(g_Ah + e + 2) = __floats2half2_rn(v.z, v.w);
    }
}

// ---------------------------------------------------------------------------
// index handling, counts, CSR build
// ---------------------------------------------------------------------------
__device__ __forceinline__ int ldidx(const void* p, long i) {
    return g_idx64 ? (int)((const long long*)p)[i] : ((const int*)p)[i];
}

__global__ void initdet_k(const unsigned* __restrict__ w) {
    int i = blockIdx.x * blockDim.x + threadIdx.x;
    if (i == 0) {
        int is64 = 1;
        for (int k = 0; k < 32; k++)
            if (w[2 * k + 1] != 0u) { is64 = 0; break; }
        g_idx64 = is64;
    }
    if (i < NN * RR) g_cnt[i] = 0;
    if (i < NN) g_fill[i] = 0;
    if (i < HD) { g_bnsum[i] = 0.f; g_bnsq[i] = 0.f; }
}

__global__ void count_k(const void* __restrict__ ei, const void* __restrict__ et) {
    int e = blockIdx.x * blockDim.x + threadIdx.x;
    if (e >= EE) return;
    int dst = ldidx(ei, (long)EE + e);
    int r   = ldidx(et, e);
    atomicAdd(&g_cnt[dst * RR + r], 1);
}

__global__ void scanA_k() {
    __shared__ int s[256];
    int i = blockIdx.x * 256 + threadIdx.x;
    int d = 0;
    if (i < NN) {
#pragma unroll
        for (int r = 0; r < RR; r++) d += g_cnt[i * RR + r];
        g_deg[i] = d;
    }
    s[threadIdx.x] = d;
    __syncthreads();
    for (int st = 128; st; st >>= 1) {
        if (threadIdx.x < st) s[threadIdx.x] += s[threadIdx.x + st];
        __syncthreads();
    }
    if (threadIdx.x == 0) g_bsum[blockIdx.x] = s[0];
}

__global__ void scanC_k() {
    __shared__ int s[256];
    __shared__ int sprev;
    int i = blockIdx.x * 256 + threadIdx.x;
    int v = (i < NN) ? g_deg[i] : 0;
    s[threadIdx.x] = v;
    int pb = (threadIdx.x < blockIdx.x) ? g_bsum[threadIdx.x] : 0;
    __syncthreads();
    for (int st = 1; st < 256; st <<= 1) {
        int t = (threadIdx.x >= st) ? s[threadIdx.x - st] : 0;
        __syncthreads();
        s[threadIdx.x] += t;
        __syncthreads();
    }
#pragma unroll
    for (int o = 16; o; o >>= 1) pb += __shfl_xor_sync(0xffffffffu, pb, o);
    if (threadIdx.x == 0) sprev = 0;
    __syncthreads();
    if ((threadIdx.x & 31) == 0) atomicAdd(&sprev, pb);
    __syncthreads();
    if (i < NN) g_off[i] = sprev + s[threadIdx.x] - v;
}

__global__ void bucket_k(const void* __restrict__ ei, const void* __restrict__ et) {
    int e = blockIdx.x * blockDim.x + threadIdx.x;
    if (e >= EE) return;
    int src = ldidx(ei, e);
    int dst = ldidx(ei, (long)EE + e);
    int r   = ldidx(et, e);
    int pos = g_off[dst] + atomicAdd(&g_fill[dst], 1);
    g_csr[pos] = (unsigned)src | ((unsigned)r << 24);
}

// ---------------------------------------------------------------------------
// warp-per-dst RGCN aggregation (fp16 gather, 4-edge unroll) + fused h split
// ---------------------------------------------------------------------------
__global__ void agg1csr_k() {
    int dst = (blockIdx.x * blockDim.x + threadIdx.x) >> 5;
    int lane = threadIdx.x & 31;
    if (dst >= NN) return;
    float invc = 0.f;
    if (lane < RR) {
        int c = g_cnt[dst * RR + lane];
        invc = 1.0f / (float)max(c, 1);
    }
    const int off = g_off[dst], deg = g_deg[dst];
    float4 acc = {0.f, 0.f, 0.f, 0.f};
    for (int base = 0; base < deg; base += 32) {
        unsigned pk = 0;
        int m = min(32, deg - base);
        if (lane < m) pk = g_csr[off + base + lane];
        int j = 0;
        for (; j + 4 <= m; j += 4) {
            long s[4]; float w[4]; uint2 mv[4];
#pragma unroll
            for (int u = 0; u < 4; u++) {
                unsigned p = __shfl_sync(0xffffffffu, pk, j + u);
                s[u] = (long)(p & 0xFFFFFF);
                int r = p >> 24;
                w[u] = __shfl_sync(0xffffffffu, invc, r);
                mv[u] = *(const uint2*)(g_xWh + s[u] * 1024 + r * 128 + lane * 4);
            }
#pragma unroll
            for (int u = 0; u < 4; u++) {
                float2 a = __half22float2(*(__half2*)&mv[u].x);
                float2 b = __half22float2(*(__half2*)&mv[u].y);
                acc.x += w[u] * a.x; acc.y += w[u] * a.y;
                acc.z += w[u] * b.x; acc.w += w[u] * b.y;
            }
        }
        for (; j < m; j++) {
            unsigned p = __shfl_sync(0xffffffffu, pk, j);
            long s0 = (long)(p & 0xFFFFFF);
            int r0 = p >> 24;
            float w0 = __shfl_sync(0xffffffffu, invc, r0);
            uint2 m0 = *(const uint2*)(g_xWh + s0 * 1024 + r0 * 128 + lane * 4);
            float2 a0 = __half22float2(*(__half2*)&m0.x);
            float2 b0 = __half22float2(*(__half2*)&m0.y);
            acc.x += w0 * a0.x; acc.y += w0 * a0.y;
            acc.z += w0 * b0.x; acc.w += w0 * b0.y;
        }
    }
    float4 cur = g_h[(long)dst * 32 + lane];
    cur.x += acc.x; cur.y += acc.y; cur.z += acc.z; cur.w += acc.w;
    __half hx = __float2half_rn(cur.x), hy = __float2half_rn(cur.y);
    __half hz = __float2half_rn(cur.z), hw = __float2half_rn(cur.w);
    __half2* hp = (__half2*)(g_Hh + (size_t)dst * HD + lane * 4);
    hp[0] = __half2{hx, hy}; hp[1] = __half2{hz, hw};
    __half2* lp = (__half2*)(g_Hl + (size_t)dst * HD + lane * 4);
    lp[0] = __floats2half2_rn(cur.x - __half2float(hx), cur.y - __half2float(hy));
    lp[1] = __floats2half2_rn(cur.z - __half2float(hz), cur.w - __half2float(hw));
}

// ---------------------------------------------------------------------------
// warp-per-dst fused attention (4-edge unroll, __expf) + fused BN statistics.
// PDL-dependent on GEMM2: CSR reads pre-sync, q/kv reads post-sync.
// ---------------------------------------------------------------------------
__global__ void attn_k(float* __restrict__ out) {
    __shared__ float sbn[HD], sbq[HD];
    const int tid = threadIdx.x;
    if (tid < HD) { sbn[tid] = 0.f; sbq[tid] = 0.f; }

    int dst = (blockIdx.x * blockDim.x + tid) >> 5;
    int lane = tid & 31;
    const int off = g_off[dst], deg = g_deg[dst];   // branch-A data (old)
    __syncthreads();

    cudaGridDependencySynchronize();   // wait for GEMM2 outputs (q, kv, skip)

    const float4 qv = g_q[(long)dst * 32 + lane];
    float4 accv = {0.f, 0.f, 0.f, 0.f};
    float ssum = 0.f;
    const float sc = 0.08838834764831845f;  // 1/sqrt(128)
    for (int base = 0; base < deg; base += 32) {
        unsigned pk = 0;
        int m = min(32, deg - base);
        if (lane < m) pk = g_csr[off + base + lane];
        int j = 0;
        for (; j + 4 <= m; j += 4) {
            uint4 r[4]; float d[4];
#pragma unroll
            for (int u = 0; u < 4; u++) {
                unsigned p = __shfl_sync(0xffffffffu, pk, j + u);
                r[u] = *(const uint4*)(g_kvh + (long)(p & 0xFFFFFF) * 256 + lane * 8);
            }
#pragma unroll
            for (int u = 0; u < 4; u++) {
                float2 ka = __half22float2(*(__half2*)&r[u].x);
                float2 kb = __half22float2(*(__half2*)&r[u].y);
                d[u] = qv.x * ka.x + qv.y * ka.y + qv.z * kb.x + qv.w * kb.y;
            }
#pragma unroll
            for (int o = 16; o; o >>= 1) {
#pragma unroll
                for (int u = 0; u < 4; u++)
                    d[u] += __shfl_xor_sync(0xffffffffu, d[u], o);
            }
#pragma unroll
            for (int u = 0; u < 4; u++) {
                float e = __expf(d[u] * sc);
                float2 va = __half22float2(*(__half2*)&r[u].z);
                float2 vb = __half22float2(*(__half2*)&r[u].w);
                ssum += e;
                accv.x += e * va.x; accv.y += e * va.y;
                accv.z += e * vb.x; accv.w += e * vb.y;
            }
        }
        for (; j < m; j++) {
            unsigned p = __shfl_sync(0xffffffffu, pk, j);
            uint4 r0 = *(const uint4*)(g_kvh + (long)(p & 0xFFFFFF) * 256 + lane * 8);
            float2 ka = __half22float2(*(__half2*)&r0.x);
            float2 kb = __half22float2(*(__half2*)&r0.y);
            float d0 = qv.x * ka.x + qv.y * ka.y + qv.z * kb.x + qv.w * kb.y;
#pragma unroll
            for (int o = 16; o; o >>= 1) d0 += __shfl_xor_sync(0xffffffffu, d0, o);
            float e = __expf(d0 * sc);
            float2 va = __half22float2(*(__half2*)&r0.z);
            float2 vb = __half22float2(*(__half2*)&r0.w);
            ssum += e;
            accv.x += e * va.x; accv.y += e * va.y;
            accv.z += e * vb.x; accv.w += e * vb.y;
        }
    }
    float inv = 1.0f / fmaxf(ssum, 1e-16f);
    float4* op = (float4*)(out + (long)dst * 128) + lane;
    float4 cur = *op;
    cur.x += accv.x * inv; cur.y += accv.y * inv;
    cur.z += accv.z * inv; cur.w += accv.w * inv;
    *op = cur;

    cudaTriggerProgrammaticLaunchCompletion();

    atomicAdd(&sbn[lane * 4 + 0], cur.x);
    atomicAdd(&sbn[lane * 4 + 1], cur.y);
    atomicAdd(&sbn[lane * 4 + 2], cur.z);
    atomicAdd(&sbn[lane * 4 + 3], cur.w);
    atomicAdd(&sbq[lane * 4 + 0], cur.x * cur.x);
    atomicAdd(&sbq[lane * 4 + 1], cur.y * cur.y);
    atomicAdd(&sbq[lane * 4 + 2], cur.z * cur.z);
    atomicAdd(&sbq[lane * 4 + 3], cur.w * cur.w);
    __syncthreads();
    if (tid < HD) {
        atomicAdd(&g_bnsum[tid], sbn[tid]);
        atomicAdd(&g_bnsq[tid], sbq[tid]);
    }
}

// ---------------------------------------------------------------------------
// BN finalize + apply + LeakyReLU (float4). PDL-dependent on attn.
// ---------------------------------------------------------------------------
__global__ void bnapply_k(float* __restrict__ out,
                          const float* __restrict__ gamma,
                          const float* __restrict__ beta) {
    cudaGridDependencySynchronize();   // wait for attn (stats + out)
    __shared__ float ssc[HD], ssh[HD];
    if (threadIdx.x < HD) {
        int c = threadIdx.x;
        float mu  = g_bnsum[c] * (1.0f / NN);
        float var = g_bnsq[c] * (1.0f / NN) - mu * mu;
        var = fmaxf(var, 0.f);
        float inv = rsqrtf(var + 1e-5f);
        float scv = gamma[c] * inv;
        ssc[c] = scv;
        ssh[c] = beta[c] - mu * scv;
    }
    __syncthreads();
    long i = ((long)blockIdx.x * blockDim.x + threadIdx.x) * 4;
    int c = (int)(i & 127);
    float4 v = *(float4*)(out + i);
    float y0 = v.x * ssc[c + 0] + ssh[c + 0];
    float y1 = v.y * ssc[c + 1] + ssh[c + 1];
    float y2 = v.z * ssc[c + 2] + ssh[c + 2];
    float y3 = v.w * ssc[c + 3] + ssh[c + 3];
    v.x = (y0 >= 0.f) ? y0 : 0.01f * y0;
    v.y = (y1 >= 0.f) ? y1 : 0.01f * y1;
    v.z = (y2 >= 0.f) ? y2 : 0.01f * y2;
    v.w = (y3 >= 0.f) ? y3 : 0.01f * y3;
    *(float4*)(out + i) = v;
}

// ---------------------------------------------------------------------------
// PDL launch helper: dependent kernel with programmatic stream serialization
// ---------------------------------------------------------------------------
template <typename F, typename... A>
static void pdl_launch(F f, dim3 g, dim3 b, size_t sh, cudaStream_t st, A... args) {
    cudaLaunchConfig_t cfg{};
    cfg.gridDim = g; cfg.blockDim = b; cfg.dynamicSmemBytes = sh; cfg.stream = st;
    cudaLaunchAttribute at[1];
    at[0].id = cudaLaunchAttributeProgrammaticStreamSerialization;
    at[0].val.programmaticStreamSerializationAllowed = 1;
    cfg.attrs = at; cfg.numAttrs = 1;
    cudaLaunchKernelEx(&cfg, f, args...);
}

// ---------------------------------------------------------------------------
extern "C" void kernel_launch(void* const* d_in, const int* in_sizes, int n_in,
                              void* d_out, int out_size)
{
    const float* x      = (const float*)d_in[0];
    const void*  ei     = d_in[1];
    const void*  et     = d_in[2];
    const float* W_rel  = (const float*)d_in[3];
    const float* W_root = (const float*)d_in[4];
    const float* b1     = (const float*)d_in[5];
    const float* Wq     = (const float*)d_in[6];
    const float* bq     = (const float*)d_in[7];
    const float* Wk     = (const float*)d_in[8];
    const float* bk     = (const float*)d_in[9];
    const float* Wv     = (const float*)d_in[10];
    const float* bv     = (const float*)d_in[11];
    const float* Wskip  = (const float*)d_in[12];
    const float* bskip  = (const float*)d_in[13];
    const float* gamma  = (const float*)d_in[14];
    const float* beta   = (const float*)d_in[15];
    float* out = (float*)d_out;

    void *xwhp, *hp, *qp, *kvp, *ahp, *hhp, *hlp, *wallp, *wqhp;
    cudaGetSymbolAddress(&xwhp, g_xWh);
    cudaGetSymbolAddress(&hp,  g_h);
    cudaGetSymbolAddress(&qp,  g_q);
    cudaGetSymbolAddress(&kvp, g_kvh);
    cudaGetSymbolAddress(&ahp, g_Ah);
    cudaGetSymbolAddress(&hhp, g_Hh);
    cudaGetSymbolAddress(&hlp, g_Hl);
    cudaGetSymbolAddress(&wallp, g_Wall);
    cudaGetSymbolAddress(&wqhp, g_Wqk_hi);

    const int SMEM_BYTES = 3 * 32768;
    cudaFuncSetAttribute(mmagemm_k<1>, cudaFuncAttributeMaxDynamicSharedMemorySize, SMEM_BYTES);
    cudaFuncSetAttribute(mmagemm_k<2>, cudaFuncAttributeMaxDynamicSharedMemorySize, SMEM_BYTES);

    const int rowTiles = (NN + 127) / 128;  // 391

    cudaStream_t s1;
    cudaStreamCreateWithFlags(&s1, cudaStreamNonBlocking);
    cudaEvent_t evF, evJ;
    cudaEventCreateWithFlags(&evF, cudaEventDisableTiming);
    cudaEventCreateWithFlags(&evJ, cudaEventDisableTiming);

    cudaEventRecord(evF, 0);
    cudaStreamWaitEvent(s1, evF, 0);
    // ---- branch A: CSR build ----
    initdet_k<<<(NN * RR + 255) / 256, 256, 0, s1>>>((const unsigned*)ei);
    count_k  <<<(EE + 255) / 256, 256, 0, s1>>>(ei, et);
    scanA_k  <<<NBS, 256, 0, s1>>>();
    scanC_k  <<<NBS, 256, 0, s1>>>();
    bucket_k <<<(EE + 255) / 256, 256, 0, s1>>>(ei, et);
    cudaEventRecord(evJ, s1);

    // ---- branch B: merged weight-prep + x conversion, then GEMM1 (PDL) ----
    const int PCT = 9 * GD * HD + 4 * HD * HD + NN * GD / 4;
    prepcvt_k<<<(PCT + 255) / 256, 256>>>(W_rel, W_root, Wq, Wk, Wv, Wskip, x);

    OutPack p1{};
    for (int zz = 0; zz < 8; zz++)
        p1.d[zz] = { (void*)((__half*)xwhp + zz * 128), nullptr, 1024, 1 };
    p1.d[8] = { hp, b1, (long)HD, 0 };
    pdl_launch(mmagemm_k<1>, dim3(9, rowTiles), dim3(256), SMEM_BYTES, 0,
               (const __half*)ahp, (const __half*)nullptr, (const __half*)wallp,
               p1, (int)NN, (int)GD, (long)HD * GD);

    cudaStreamWaitEvent(0, evJ, 0);

    // RGCN mean aggregation + fused h hi/lo split (normal launch: event join)
    agg1csr_k<<<(NN * 32) / 256, 256>>>();

    // GEMM2 (2-pass fp16 A-split), PDL on agg1
    OutPack p2{};
    p2.d[0] = { qp,  bq,    (long)HD, 0 };
    p2.d[1] = { kvp, bk,    256,      2 };
    p2.d[2] = { kvp, bv,    256,      3 };
    p2.d[3] = { out, bskip, (long)HD, 0 };
    pdl_launch(mmagemm_k<2>, dim3(4, rowTiles), dim3(256), SMEM_BYTES, 0,
               (const __half*)hhp, (const __half*)hlp, (const __half*)wqhp,
               p2, (int)NN, (int)HD, (long)HD * HD);

    // fused attention + BN stats, PDL on GEMM2
    pdl_launch(attn_k, dim3((NN * 32) / 256), dim3(256), 0, 0, out);

    // BN finalize+apply + LeakyReLU, PDL on attn
    pdl_launch(bnapply_k, dim3((NN * HD / 4) / 256), dim3(256), 0, 0,
               out, gamma, beta);
}

// round 14
// speedup vs baseline: 1.1089x; 1.1089x over previous
#include <cuda_runtime.h>
#include <cuda_fp16.h>
#include <cstdint>

// ---------------------------------------------------------------------------
// GNN_6837587935613: RGCN(mean, R=8) -> TransformerConv(1 head) -> BN+LeakyReLU
// N=50000, E=800000, G_DIM=512, H1=H2=128, R=8
// Round 14: revert PDL/.ca regression (back to R12 structure); GEMM2 single
//           pass fp16 (calibrated error budget: ~8.7e-4 < 1e-3).
// ---------------------------------------------------------------------------

#define NN   50000
#define NPAD 50176
#define EE   800000
#define GD   512
#define HD   128
#define RR   8
#define NBS  196   // ceil(NN/256) scan blocks

// ---- scratch (device globals) ----
__device__ __align__(128) __half g_xWh[(size_t)NN * 1024];  // [N, 8*128] fp16
__device__ float4   g_h [(size_t)NN * 32];    // [N, 128] f32 (root+bias)
__device__ float4   g_q [(size_t)NN * 32];    // [N, 128] f32
__device__ __align__(128) __half g_kvh[(size_t)NN * 256];   // [N][32 grp][k4,v4]
__device__ int      g_cnt[NN * RR];
__device__ int      g_deg[NN];
__device__ int      g_off[NN];
__device__ int      g_fill[NN];
__device__ int      g_bsum[256];
__device__ unsigned g_csr[EE];
__device__ float    g_bnsum[HD];
__device__ float    g_bnsq[HD];
__device__ int      g_idx64;

// fp16 operands (row-padded; padding stays zero from load-time .bss init)
__device__ __align__(128) __half g_Ah[(size_t)NPAD * GD];
__device__ __align__(128) __half g_Hh[(size_t)NPAD * HD];
// K-major fp16 weights
__device__ __align__(128) __half g_Wall[9 * HD * GD];       // 8 relations + root
__device__ __align__(128) __half g_Wqk[4 * HD * HD];

// ---------------------------------------------------------------------------
__device__ __forceinline__ uint32_t smem_u32(const void* p) {
    uint32_t a;
    asm("{ .reg .u64 t; cvta.to.shared.u64 t, %1; cvt.u32.u64 %0, t; }"
        : "=r"(a) : "l"(p));
    return a;
}
#define SWZ(o) ((o) ^ (((o) >> 3) & 0x70))

#define CP_ASYNC16(dst, src) \
    asm volatile("cp.async.cg.shared.global [%0], [%1], 16;" :: "r"(dst), "l"(src))
#define CP_COMMIT()  asm volatile("cp.async.commit_group;" ::: "memory")
#define CP_WAIT0()   asm volatile("cp.async.wait_group 0;" ::: "memory")
#define CP_WAIT1()   asm volatile("cp.async.wait_group 1;" ::: "memory")

#define LDSM_X4(r, a)                                                        \
    asm volatile("ldmatrix.sync.aligned.m8n8.x4.shared.b16 {%0,%1,%2,%3}, [%4];" \
        : "=r"((r)[0]), "=r"((r)[1]), "=r"((r)[2]), "=r"((r)[3]) : "r"(a))

#define MMA16816(c, a, b0, b1)                                               \
    asm volatile("mma.sync.aligned.m16n8k16.row.col.f32.f16.f16.f32 "        \
        "{%0,%1,%2,%3}, {%4,%5,%6,%7}, {%8,%9}, {%0,%1,%2,%3};"              \
        : "+f"((c)[0]), "+f"((c)[1]), "+f"((c)[2]), "+f"((c)[3])             \
        : "r"((a)[0]), "r"((a)[1]), "r"((a)[2]), "r"((a)[3]), "r"(b0), "r"(b1))

// mode: 0 = f32 plain; 1 = fp16 plain (ldc in halves); 2 = fp16 kv k-slot;
//       3 = fp16 kv v-slot (kv row = 32 groups of [k0..k3, v0..v3])
struct OutDesc { void* C; const float* bias; long ldc; int mode; };
struct OutPack { OutDesc d[9]; };

// ---------------------------------------------------------------------------
// fp16 single-pass GEMM via mma.sync, 3-stage cp.async pipeline.
// grid = (Z, ceil(M/128)), block = 256 (8 warps: 4M x 2N), smem = 3*32KB.
// Staged smem epilogue with coalesced copy-out.
// ---------------------------------------------------------------------------
__global__ void __launch_bounds__(256, 2) mmagemm_k(
    const __half* __restrict__ A, const __half* __restrict__ Ball,
    OutPack outs, int M, int K, long bzStride)
{
    extern __shared__ char smem[];
    const uint32_t sb = smem_u32(smem);
    const int tid = threadIdx.x, lane = tid & 31, wid = tid >> 5;
    const int wm = wid & 3, wn = wid >> 2;
    const int z = blockIdx.x, row0 = blockIdx.y * 128;
    const __half* B = Ball + (long)z * bzStride;

    const int NIT = K >> 6;

    float acc[2][8][4];
#pragma unroll
    for (int i = 0; i < 2; i++)
#pragma unroll
        for (int j = 0; j < 8; j++)
#pragma unroll
            for (int c = 0; c < 4; c++) acc[i][j][c] = 0.f;

    const int cr = tid >> 3, cck = tid & 7;

    auto issue = [&](int it) {
        const int k0 = it * 64;
        const uint32_t base = sb + (it % 3) * 32768;
#pragma unroll
        for (int i = 0; i < 4; i++) {
            const int r = cr + i * 32;
            CP_ASYNC16(base + SWZ(r * 128 + cck * 16),
                       A + (size_t)(row0 + r) * K + k0 + cck * 8);
            CP_ASYNC16(base + 16384 + SWZ(r * 128 + cck * 16),
                       B + (size_t)r * K + k0 + cck * 8);
        }
        CP_COMMIT();
    };

    issue(0);
    if (NIT > 1) issue(1);
    for (int it = 0; it < NIT; ++it) {
        if (it + 1 < NIT) CP_WAIT1();
        else              CP_WAIT0();
        __syncthreads();
        if (it + 2 < NIT) issue(it + 2);

        const uint32_t Ab = sb + (it % 3) * 32768;
        const uint32_t Bb = Ab + 16384;
#pragma unroll
        for (int ks = 0; ks < 4; ks++) {
            uint32_t ra[2][4];
#pragma unroll
            for (int mi = 0; mi < 2; mi++) {
                const int r = wm * 32 + mi * 16 + (lane & 15);
                const int ck = ks * 2 + (lane >> 4);
                LDSM_X4(ra[mi], Ab + SWZ(r * 128 + ck * 16));
            }
            uint32_t rb[4][4];
#pragma unroll
            for (int g = 0; g < 4; g++) {
                const int nr = wn * 64 + g * 16 + ((lane & 7) | ((lane & 16) >> 1));
                const int ck = ks * 2 + ((lane >> 3) & 1);
                LDSM_X4(rb[g], Bb + SWZ(nr * 128 + ck * 16));
            }
#pragma unroll
            for (int mi = 0; mi < 2; mi++)
#pragma unroll
                for (int g = 0; g < 4; g++) {
                    MMA16816(acc[mi][2 * g + 0], ra[mi], rb[g][0], rb[g][1]);
                    MMA16816(acc[mi][2 * g + 1], ra[mi], rb[g][2], rb[g][3]);
                }
        }
    }

    // ---- staged epilogue ----
    __syncthreads();
    const OutDesc od = outs.d[z];

    if (od.mode == 0) {
        float* st = (float*)smem;                 // [128][132] f32
#pragma unroll
        for (int mi = 0; mi < 2; mi++) {
            const int rl = wm * 32 + mi * 16 + (lane >> 2);
#pragma unroll
            for (int ni = 0; ni < 8; ni++) {
                const int cl = wn * 64 + ni * 8 + (lane & 3) * 2;
                float b0 = 0.f, b1 = 0.f;
                if (od.bias) { b0 = od.bias[cl]; b1 = od.bias[cl + 1]; }
#pragma unroll
                for (int hr = 0; hr < 2; hr++) {
                    float2 v = { acc[mi][ni][2 * hr + 0] + b0,
                                 acc[mi][ni][2 * hr + 1] + b1 };
                    *(float2*)(st + (rl + hr * 8) * 132 + cl) = v;
                }
            }
        }
        __syncthreads();
#pragma unroll
        for (int i = 0; i < 16; i++) {
            int chunk = tid + i * 256;
            int rl = chunk >> 5, c4 = chunk & 31;
            int row = row0 + rl;
            if (row < M) {
                uint4 v = *(uint4*)(st + rl * 132 + c4 * 4);
                *(uint4*)((float*)od.C + (size_t)row * od.ldc + c4 * 4) = v;
            }
        }
    } else {
        __half* st = (__half*)smem;               // [128][136] fp16
#pragma unroll
        for (int mi = 0; mi < 2; mi++) {
            const int rl = wm * 32 + mi * 16 + (lane >> 2);
#pragma unroll
            for (int ni = 0; ni < 8; ni++) {
                const int cl = wn * 64 + ni * 8 + (lane & 3) * 2;
                float b0 = 0.f, b1 = 0.f;
                if (od.bias) { b0 = od.bias[cl]; b1 = od.bias[cl + 1]; }
#pragma unroll
                for (int hr = 0; hr < 2; hr++) {
                    __half2 hv = __floats2half2_rn(acc[mi][ni][2 * hr + 0] + b0,
                                                   acc[mi][ni][2 * hr + 1] + b1);
                    *(__half2*)(st + (rl + hr * 8) * 136 + cl) = hv;
                }
            }
        }
        __syncthreads();
        if (od.mode == 1) {
#pragma unroll
            for (int i = 0; i < 8; i++) {
                int chunk = tid + i * 256;
                int rl = chunk >> 4, c4 = chunk & 15;
                int row = row0 + rl;
                if (row < M) {
                    uint4 v = *(uint4*)(st + rl * 136 + c4 * 8);
                    *(uint4*)((__half*)od.C + (size_t)row * od.ldc + c4 * 8) = v;
                }
            }
        } else {
            const int voff = (od.mode == 3) ? 4 : 0;
#pragma unroll
            for (int i = 0; i < 16; i++) {
                int chunk = tid + i * 256;
                int rl = chunk >> 5, g = chunk & 31;
                int row = row0 + rl;
                if (row < M) {
                    uint2 v = *(uint2*)(st + rl * 136 + g * 4);
                    *(uint2*)((__half*)od.C + (size_t)row * 256 + g * 8 + voff) = v;
                }
            }
        }
    }
}

// ---------------------------------------------------------------------------
// merged weight prep + x->fp16 conversion (one launch)
// ---------------------------------------------------------------------------
__global__ void prepcvt_k(const float* __restrict__ Wrel, const float* __restrict__ Wroot,
                          const float* __restrict__ Wq, const float* __restrict__ Wk,
                          const float* __restrict__ Wv, const float* __restrict__ Ws,
                          const float* __restrict__ x) {
    const int T0 = 9 * GD * HD;
    const int T1 = T0 + 4 * HD * HD;
    const int T2 = T1 + NN * GD / 4;
    int i = blockIdx.x * blockDim.x + threadIdx.x;
    if (i >= T2) return;
    if (i < T0) {
        int z = i >> 16, rem = i & 65535;
        int k = rem >> 7, n = rem & 127;
        float v = (z < 8) ? Wrel[(long)z * 65536 + k * 128 + n] : Wroot[k * 128 + n];
        g_Wall[(long)z * 65536 + n * 512 + k] = __float2half(v);
    } else if (i < T1) {
        int j = i - T0;
        int m = j >> 14, jj = j & 16383;
        int k = jj >> 7, n = jj & 127;
        float v = (m == 0) ? Wq[jj] : (m == 1) ? Wk[jj] : (m == 2) ? Wv[jj] : Ws[jj];
        g_Wqk[(long)m * 16384 + n * 128 + k] = __float2half_rn(v);
    } else {
        long e = (long)(i - T1) * 4;
        float4 v = *(const float4*)(x + e);
        *(__half2*)(g_Ah + e)     = __floats2half2_rn(v.x, v.y);
        *(__half2*)(g_Ah + e + 2) = __floats2half2_rn(v.z, v.w);
    }
}

// ---------------------------------------------------------------------------
// index handling, counts, CSR build
// ---------------------------------------------------------------------------
__device__ __forceinline__ int ldidx(const void* p, long i) {
    return g_idx64 ? (int)((const long long*)p)[i] : ((const int*)p)[i];
}

__global__ void initdet_k(const unsigned* __restrict__ w) {
    int i = blockIdx.x * blockDim.x + threadIdx.x;
    if (i == 0) {
        int is64 = 1;
        for (int k = 0; k < 32; k++)
            if (w[2 * k + 1] != 0u) { is64 = 0; break; }
        g_idx64 = is64;
    }
    if (i < NN * RR) g_cnt[i] = 0;
    if (i < NN) g_fill[i] = 0;
    if (i < HD) { g_bnsum[i] = 0.f; g_bnsq[i] = 0.f; }
}

__global__ void count_k(const void* __restrict__ ei, const void* __restrict__ et) {
    int e = blockIdx.x * blockDim.x + threadIdx.x;
    if (e >= EE) return;
    int dst = ldidx(ei, (long)EE + e);
    int r   = ldidx(et, e);
    atomicAdd(&g_cnt[dst * RR + r], 1);
}

__global__ void scanA_k() {
    __shared__ int s[256];
    int i = blockIdx.x * 256 + threadIdx.x;
    int d = 0;
    if (i < NN) {
#pragma unroll
        for (int r = 0; r < RR; r++) d += g_cnt[i * RR + r];
        g_deg[i] = d;
    }
    s[threadIdx.x] = d;
    __syncthreads();
    for (int st = 128; st; st >>= 1) {
        if (threadIdx.x < st) s[threadIdx.x] += s[threadIdx.x + st];
        __syncthreads();
    }
    if (threadIdx.x == 0) g_bsum[blockIdx.x] = s[0];
}

__global__ void scanC_k() {
    __shared__ int s[256];
    __shared__ int sprev;
    int i = blockIdx.x * 256 + threadIdx.x;
    int v = (i < NN) ? g_deg[i] : 0;
    s[threadIdx.x] = v;
    int pb = (threadIdx.x < blockIdx.x) ? g_bsum[threadIdx.x] : 0;
    __syncthreads();
    for (int st = 1; st < 256; st <<= 1) {
        int t = (threadIdx.x >= st) ? s[threadIdx.x - st] : 0;
        __syncthreads();
        s[threadIdx.x] += t;
        __syncthreads();
    }
#pragma unroll
    for (int o = 16; o; o >>= 1) pb += __shfl_xor_sync(0xffffffffu, pb, o);
    if (threadIdx.x == 0) sprev = 0;
    __syncthreads();
    if ((threadIdx.x & 31) == 0) atomicAdd(&sprev, pb);
    __syncthreads();
    if (i < NN) g_off[i] = sprev + s[threadIdx.x] - v;
}

__global__ void bucket_k(const void* __restrict__ ei, const void* __restrict__ et) {
    int e = blockIdx.x * blockDim.x + threadIdx.x;
    if (e >= EE) return;
    int src = ldidx(ei, e);
    int dst = ldidx(ei, (long)EE + e);
    int r   = ldidx(et, e);
    int pos = g_off[dst] + atomicAdd(&g_fill[dst], 1);
    g_csr[pos] = (unsigned)src | ((unsigned)r << 24);
}

// ---------------------------------------------------------------------------
// warp-per-dst RGCN aggregation (fp16 gather, 4-edge unroll) + fused h->fp16
// ---------------------------------------------------------------------------
__global__ void agg1csr_k() {
    int dst = (blockIdx.x * blockDim.x + threadIdx.x) >> 5;
    int lane = threadIdx.x & 31;
    if (dst >= NN) return;
    float invc = 0.f;
    if (lane < RR) {
        int c = g_cnt[dst * RR + lane];
        invc = 1.0f / (float)max(c, 1);
    }
    const int off = g_off[dst], deg = g_deg[dst];
    float4 acc = {0.f, 0.f, 0.f, 0.f};
    for (int base = 0; base < deg; base += 32) {
        unsigned pk = 0;
        int m = min(32, deg - base);
        if (lane < m) pk = g_csr[off + base + lane];
        int j = 0;
        for (; j + 4 <= m; j += 4) {
            long s[4]; float w[4]; uint2 mv[4];
#pragma unroll
            for (int u = 0; u < 4; u++) {
                unsigned p = __shfl_sync(0xffffffffu, pk, j + u);
                s[u] = (long)(p & 0xFFFFFF);
                int r = p >> 24;
                w[u] = __shfl_sync(0xffffffffu, invc, r);
                mv[u] = *(const uint2*)(g_xWh + s[u] * 1024 + r * 128 + lane * 4);
            }
#pragma unroll
            for (int u = 0; u < 4; u++) {
                float2 a = __half22float2(*(__half2*)&mv[u].x);
                float2 b = __half22float2(*(__half2*)&mv[u].y);
                acc.x += w[u] * a.x; acc.y += w[u] * a.y;
                acc.z += w[u] * b.x; acc.w += w[u] * b.y;
            }
        }
        for (; j < m; j++) {
            unsigned p = __shfl_sync(0xffffffffu, pk, j);
            long s0 = (long)(p & 0xFFFFFF);
            int r0 = p >> 24;
            float w0 = __shfl_sync(0xffffffffu, invc, r0);
            uint2 m0 = *(const uint2*)(g_xWh + s0 * 1024 + r0 * 128 + lane * 4);
            float2 a0 = __half22float2(*(__half2*)&m0.x);
            float2 b0 = __half22float2(*(__half2*)&m0.y);
            acc.x += w0 * a0.x; acc.y += w0 * a0.y;
            acc.z += w0 * b0.x; acc.w += w0 * b0.y;
        }
    }
    float4 cur = g_h[(long)dst * 32 + lane];
    cur.x += acc.x; cur.y += acc.y; cur.z += acc.z; cur.w += acc.w;
    __half2* hp = (__half2*)(g_Hh + (size_t)dst * HD + lane * 4);
    hp[0] = __floats2half2_rn(cur.x, cur.y);
    hp[1] = __floats2half2_rn(cur.z, cur.w);
}

// ---------------------------------------------------------------------------
// warp-per-dst fused attention (4-edge unroll, __expf) + fused BN statistics
// ---------------------------------------------------------------------------
__global__ void attn_k(float* __restrict__ out) {
    __shared__ float sbn[HD], sbq[HD];
    const int tid = threadIdx.x;
    if (tid < HD) { sbn[tid] = 0.f; sbq[tid] = 0.f; }
    __syncthreads();

    int dst = (blockIdx.x * blockDim.x + tid) >> 5;
    int lane = tid & 31;
    const float4 qv = g_q[(long)dst * 32 + lane];
    const int off = g_off[dst], deg = g_deg[dst];
    float4 accv = {0.f, 0.f, 0.f, 0.f};
    float ssum = 0.f;
    const float sc = 0.08838834764831845f;  // 1/sqrt(128)
    for (int base = 0; base < deg; base += 32) {
        unsigned pk = 0;
        int m = min(32, deg - base);
        if (lane < m) pk = g_csr[off + base + lane];
        int j = 0;
        for (; j + 4 <= m; j += 4) {
            uint4 r[4]; float d[4];
#pragma unroll
            for (int u = 0; u < 4; u++) {
                unsigned p = __shfl_sync(0xffffffffu, pk, j + u);
                r[u] = *(const uint4*)(g_kvh + (long)(p & 0xFFFFFF) * 256 + lane * 8);
            }
#pragma unroll
            for (int u = 0; u < 4; u++) {
                float2 ka = __half22float2(*(__half2*)&r[u].x);
                float2 kb = __half22float2(*(__half2*)&r[u].y);
                d[u] = qv.x * ka.x + qv.y * ka.y + qv.z * kb.x + qv.w * kb.y;
            }
#pragma unroll
            for (int o = 16; o; o >>= 1) {
#pragma unroll
                for (int u = 0; u < 4; u++)
                    d[u] += __shfl_xor_sync(0xffffffffu, d[u], o);
            }
#pragma unroll
            for (int u = 0; u < 4; u++) {
                float e = __expf(d[u] * sc);
                float2 va = __half22float2(*(__half2*)&r[u].z);
                float2 vb = __half22float2(*(__half2*)&r[u].w);
                ssum += e;
                accv.x += e * va.x; accv.y += e * va.y;
                accv.z += e * vb.x; accv.w += e * vb.y;
            }
        }
        for (; j < m; j++) {
            unsigned p = __shfl_sync(0xffffffffu, pk, j);
            uint4 r0 = *(const uint4*)(g_kvh + (long)(p & 0xFFFFFF) * 256 + lane * 8);
            float2 ka = __half22float2(*(__half2*)&r0.x);
            float2 kb = __half22float2(*(__half2*)&r0.y);
            float d0 = qv.x * ka.x + qv.y * ka.y + qv.z * kb.x + qv.w * kb.y;
#pragma unroll
            for (int o = 16; o; o >>= 1) d0 += __shfl_xor_sync(0xffffffffu, d0, o);
            float e = __expf(d0 * sc);
            float2 va = __half22float2(*(__half2*)&r0.z);
            float2 vb = __half22float2(*(__half2*)&r0.w);
            ssum += e;
            accv.x += e * va.x; accv.y += e * va.y;
            accv.z += e * vb.x; accv.w += e * vb.y;
        }
    }
    float inv = 1.0f / fmaxf(ssum, 1e-16f);
    float4* op = (float4*)(out + (long)dst * 128) + lane;
    float4 cur = *op;
    cur.x += accv.x * inv; cur.y += accv.y * inv;
    cur.z += accv.z * inv; cur.w += accv.w * inv;
    *op = cur;

    atomicAdd(&sbn[lane * 4 + 0], cur.x);
    atomicAdd(&sbn[lane * 4 + 1], cur.y);
    atomicAdd(&sbn[lane * 4 + 2], cur.z);
    atomicAdd(&sbn[lane * 4 + 3], cur.w);
    atomicAdd(&sbq[lane * 4 + 0], cur.x * cur.x);
    atomicAdd(&sbq[lane * 4 + 1], cur.y * cur.y);
    atomicAdd(&sbq[lane * 4 + 2], cur.z * cur.z);
    atomicAdd(&sbq[lane * 4 + 3], cur.w * cur.w);
    __syncthreads();
    if (tid < HD) {
        atomicAdd(&g_bnsum[tid], sbn[tid]);
        atomicAdd(&g_bnsq[tid], sbq[tid]);
    }
}

// ---------------------------------------------------------------------------
// BN finalize + apply in one kernel + LeakyReLU (float4 per thread)
// ---------------------------------------------------------------------------
__global__ void bnapply_k(float* __restrict__ out,
                          const float* __restrict__ gamma,
                          const float* __restrict__ beta) {
    __shared__ float ssc[HD], ssh[HD];
    if (threadIdx.x < HD) {
        int c = threadIdx.x;
        float mu  = g_bnsum[c] * (1.0f / NN);
        float var = g_bnsq[c] * (1.0f / NN) - mu * mu;
        var = fmaxf(var, 0.f);
        float inv = rsqrtf(var + 1e-5f);
        float scv = gamma[c] * inv;
        ssc[c] = scv;
        ssh[c] = beta[c] - mu * scv;
    }
    __syncthreads();
    long i = ((long)blockIdx.x * blockDim.x + threadIdx.x) * 4;
    int c = (int)(i & 127);
    float4 v = *(float4*)(out + i);
    float y0 = v.x * ssc[c + 0] + ssh[c + 0];
    float y1 = v.y * ssc[c + 1] + ssh[c + 1];
    float y2 = v.z * ssc[c + 2] + ssh[c + 2];
    float y3 = v.w * ssc[c + 3] + ssh[c + 3];
    v.x = (y0 >= 0.f) ? y0 : 0.01f * y0;
    v.y = (y1 >= 0.f) ? y1 : 0.01f * y1;
    v.z = (y2 >= 0.f) ? y2 : 0.01f * y2;
    v.w = (y3 >= 0.f) ? y3 : 0.01f * y3;
    *(float4*)(out + i) = v;
}

// ---------------------------------------------------------------------------
extern "C" void kernel_launch(void* const* d_in, const int* in_sizes, int n_in,
                              void* d_out, int out_size)
{
    const float* x      = (const float*)d_in[0];
    const void*  ei     = d_in[1];
    const void*  et     = d_in[2];
    const float* W_rel  = (const float*)d_in[3];
    const float* W_root = (const float*)d_in[4];
    const float* b1     = (const float*)d_in[5];
    const float* Wq     = (const float*)d_in[6];
    const float* bq     = (const float*)d_in[7];
    const float* Wk     = (const float*)d_in[8];
    const float* bk     = (const float*)d_in[9];
    const float* Wv     = (const float*)d_in[10];
    const float* bv     = (const float*)d_in[11];
    const float* Wskip  = (const float*)d_in[12];
    const float* bskip  = (const float*)d_in[13];
    const float* gamma  = (const float*)d_in[14];
    const float* beta   = (const float*)d_in[15];
    float* out = (float*)d_out;

    void *xwhp, *hp, *qp, *kvp, *ahp, *hhp, *wallp, *wqkp;
    cudaGetSymbolAddress(&xwhp, g_xWh);
    cudaGetSymbolAddress(&hp,  g_h);
    cudaGetSymbolAddress(&qp,  g_q);
    cudaGetSymbolAddress(&kvp, g_kvh);
    cudaGetSymbolAddress(&ahp, g_Ah);
    cudaGetSymbolAddress(&hhp, g_Hh);
    cudaGetSymbolAddress(&wallp, g_Wall);
    cudaGetSymbolAddress(&wqkp, g_Wqk);

    const int SMEM_BYTES = 3 * 32768;
    cudaFuncSetAttribute(mmagemm_k, cudaFuncAttributeMaxDynamicSharedMemorySize, SMEM_BYTES);

    const int rowTiles = (NN + 127) / 128;  // 391

    // fork/join: CSR build (branch A) concurrent with prep+GEMM1 (branch B)
    cudaStream_t s1;
    cudaStreamCreateWithFlags(&s1, cudaStreamNonBlocking);
    cudaEvent_t evF, evJ;
    cudaEventCreateWithFlags(&evF, cudaEventDisableTiming);
    cudaEventCreateWithFlags(&evJ, cudaEventDisableTiming);

    cudaEventRecord(evF, 0);
    cudaStreamWaitEvent(s1, evF, 0);
    // ---- branch A: CSR build ----
    initdet_k<<<(NN * RR + 255) / 256, 256, 0, s1>>>((const unsigned*)ei);
    count_k  <<<(EE + 255) / 256, 256, 0, s1>>>(ei, et);
    scanA_k  <<<NBS, 256, 0, s1>>>();
    scanC_k  <<<NBS, 256, 0, s1>>>();
    bucket_k <<<(EE + 255) / 256, 256, 0, s1>>>(ei, et);
    cudaEventRecord(evJ, s1);

    // ---- branch B: merged weight-prep + x conversion, then GEMM1 ----
    const int PCT = 9 * GD * HD + 4 * HD * HD + NN * GD / 4;
    prepcvt_k<<<(PCT + 255) / 256, 256>>>(W_rel, W_root, Wq, Wk, Wv, Wskip, x);

    OutPack p1{};
    for (int zz = 0; zz < 8; zz++)
        p1.d[zz] = { (void*)((__half*)xwhp + zz * 128), nullptr, 1024, 1 };
    p1.d[8] = { hp, b1, (long)HD, 0 };
    mmagemm_k<<<dim3(9, rowTiles), 256, SMEM_BYTES>>>(
        (const __half*)ahp, (const __half*)wallp, p1, NN, GD, (long)HD * GD);

    cudaStreamWaitEvent(0, evJ, 0);

    // RGCN mean aggregation + fused h->fp16
    agg1csr_k<<<(NN * 32) / 256, 256>>>();

    // GEMM2 (single-pass fp16): q f32, k/v fp16 interleaved, skip -> out
    OutPack p2{};
    p2.d[0] = { qp,  bq,    (long)HD, 0 };
    p2.d[1] = { kvp, bk,    256,      2 };
    p2.d[2] = { kvp, bv,    256,      3 };
    p2.d[3] = { out, bskip, (long)HD, 0 };
    mmagemm_k<<<dim3(4, rowTiles), 256, SMEM_BYTES>>>(
        (const __half*)hhp, (const __half*)wqkp, p2, NN, HD, (long)HD * HD);

    // fused attention + BN stats
    attn_k<<<(NN * 32) / 256, 256>>>(out);

    // BN finalize+apply + LeakyReLU (float4)
    bnapply_k<<<(NN * HD / 4) / 256, 256>>>(out, gamma, beta);
}